// round 1
// baseline (speedup 1.0000x reference)
#include <cuda_runtime.h>
#include <cstdint>

// Problem constants (fixed shapes)
#define LXC 4096
#define LZC 4096
#define DAC 1024
#define SCALE 0.03125f        // 1/sqrt(1024)
#define NEG_MASKED (-31.25f)  // -1000 * SCALE (mask fill applied BEFORE scaling)

// Scratch (device globals: allocation-guard safe)
__device__ float g_q[(size_t)DAC * LXC];
__device__ float g_k[(size_t)DAC * LZC];
__device__ float g_v[(size_t)DAC * LZC];
__device__ float g_s[(size_t)LZC * LXC];
__device__ int   g_mask_is_word;   // 1 if mask is int32 0/1, 0 if byte mask

// ---------------------------------------------------------------------------
// Mask dtype detection: scan first 4096 uint32 words. If mask is byte-packed
// bool, words contain packed 0/1 bytes -> values like 0x00010100 > 1 appear
// with overwhelming probability. If int32, all words are 0 or 1.
// ---------------------------------------------------------------------------
__global__ void detect_mask_kernel(const unsigned int* __restrict__ mw) {
    __shared__ int flag;
    if (threadIdx.x == 0) flag = 1;
    __syncthreads();
    bool byte_like = false;
    for (int i = threadIdx.x; i < 4096; i += 256)
        if (mw[i] > 1u) byte_like = true;
    if (byte_like) flag = 0;   // benign same-value race
    __syncthreads();
    if (threadIdx.x == 0) g_mask_is_word = flag;
}

// ---------------------------------------------------------------------------
// SGEMM: C(MxN) = op(A) @ B [+ bias]  (all row-major, dims multiples of 128)
//   TRANS_A=0: A is (M,K) row-major.      TRANS_A=1: A is (K,M) row-major (TN).
//   EPI=0: C = acc + bias[row] (bias may be null)
//   EPI=1: masked score epilogue: C = mask ? acc*SCALE : NEG_MASKED
// Block tile 128x128, K-tile 16, 256 threads, 8x8 per thread (4+4 split).
// ---------------------------------------------------------------------------
template <int TRANS_A, int EPI>
__global__ __launch_bounds__(256, 2)
void sgemm_kernel(const float* __restrict__ A, const float* __restrict__ B,
                  float* __restrict__ C, int M, int N, int K,
                  const float* __restrict__ bias,
                  const void* __restrict__ mask)
{
    constexpr int BM = 128, BN = 128, BK = 16;
    __shared__ float As[BK][BM];
    __shared__ float Bs[BK][BN];

    const int tid = threadIdx.x;
    const int m0 = blockIdx.y * BM;
    const int n0 = blockIdx.x * BN;
    const int tx = tid & 15;   // 0..15 -> N
    const int ty = tid >> 4;   // 0..15 -> M

    float acc[8][8];
#pragma unroll
    for (int i = 0; i < 8; i++)
#pragma unroll
        for (int j = 0; j < 8; j++) acc[i][j] = 0.0f;

    for (int k0 = 0; k0 < K; k0 += BK) {
        // ---- load A tile ----
#pragma unroll
        for (int v = 0; v < 2; v++) {
            int vec = tid + v * 256;              // 512 float4 loads total
            if (TRANS_A) {
                // A is (K,M): tile rows = k, cols = m. Fully coalesced.
                int r = vec >> 5;                 // 0..15
                int c = (vec & 31) << 2;          // 0..124
                float4 a = *(const float4*)(A + (size_t)(k0 + r) * M + m0 + c);
                *(float4*)&As[r][c] = a;
            } else {
                // A is (M,K): tile rows = m (128), cols = k (16). Transpose on store.
                int r = vec >> 2;                 // 0..127
                int s = vec & 3;                  // 0..3 (4-float segment)
                float4 a = *(const float4*)(A + (size_t)(m0 + r) * K + k0 + s * 4);
                As[s * 4 + 0][r] = a.x;
                As[s * 4 + 1][r] = a.y;
                As[s * 4 + 2][r] = a.z;
                As[s * 4 + 3][r] = a.w;
            }
            // ---- load B tile (K,N): fully coalesced ----
            int rb = vec >> 5;
            int cb = (vec & 31) << 2;
            float4 b = *(const float4*)(B + (size_t)(k0 + rb) * N + n0 + cb);
            *(float4*)&Bs[rb][cb] = b;
        }
        __syncthreads();

        // ---- compute ----
#pragma unroll
        for (int kk = 0; kk < BK; kk++) {
            float4 a0 = *(const float4*)&As[kk][ty * 4];
            float4 a1 = *(const float4*)&As[kk][64 + ty * 4];
            float4 b0 = *(const float4*)&Bs[kk][tx * 4];
            float4 b1 = *(const float4*)&Bs[kk][64 + tx * 4];
            float ra[8] = {a0.x, a0.y, a0.z, a0.w, a1.x, a1.y, a1.z, a1.w};
            float rb2[8] = {b0.x, b0.y, b0.z, b0.w, b1.x, b1.y, b1.z, b1.w};
#pragma unroll
            for (int i = 0; i < 8; i++)
#pragma unroll
                for (int j = 0; j < 8; j++)
                    acc[i][j] = fmaf(ra[i], rb2[j], acc[i][j]);
        }
        __syncthreads();
    }

    // ---- epilogue ----
    int rows[8], cols[8];
#pragma unroll
    for (int t = 0; t < 4; t++) {
        rows[t]     = m0 + ty * 4 + t;
        rows[4 + t] = m0 + 64 + ty * 4 + t;
        cols[t]     = n0 + tx * 4 + t;
        cols[4 + t] = n0 + 64 + tx * 4 + t;
    }

    if (EPI == 0) {
#pragma unroll
        for (int i = 0; i < 8; i++) {
            float bval = bias ? bias[rows[i]] : 0.0f;
#pragma unroll
            for (int j = 0; j < 8; j++)
                C[(size_t)rows[i] * N + cols[j]] = acc[i][j] + bval;
        }
    } else {
        const int is_word = g_mask_is_word;
#pragma unroll
        for (int i = 0; i < 8; i++) {
#pragma unroll
            for (int j = 0; j < 8; j++) {
                size_t idx = (size_t)rows[i] * N + cols[j];
                bool mset = is_word
                    ? (((const int*)mask)[idx] != 0)
                    : (((const unsigned char*)mask)[idx] != 0);
                C[idx] = mset ? acc[i][j] * SCALE : NEG_MASKED;
            }
        }
    }
}

// ---------------------------------------------------------------------------
// In-place softmax over dim 0 (rows, lz) of S (LZ, LX) row-major.
// lane = column -> coalesced 128B/warp per row. 32 columns per block,
// 8 row-strips per column, shared reduction.
// ---------------------------------------------------------------------------
__global__ __launch_bounds__(256)
void softmax_kernel(float* __restrict__ S) {
    __shared__ float red[8][32];
    const int lane = threadIdx.x & 31;
    const int ty = threadIdx.x >> 5;           // 0..7
    const int col = blockIdx.x * 32 + lane;

    float m = -1e30f;
#pragma unroll 4
    for (int r = ty; r < LZC; r += 8)
        m = fmaxf(m, S[(size_t)r * LXC + col]);
    red[ty][lane] = m;
    __syncthreads();
#pragma unroll
    for (int j = 0; j < 8; j++) m = fmaxf(m, red[j][lane]);
    __syncthreads();

    float sum = 0.0f;
#pragma unroll 4
    for (int r = ty; r < LZC; r += 8)
        sum += __expf(S[(size_t)r * LXC + col] - m);
    red[ty][lane] = sum;
    __syncthreads();
    sum = 0.0f;
#pragma unroll
    for (int j = 0; j < 8; j++) sum += red[j][lane];
    const float inv = 1.0f / sum;

#pragma unroll 4
    for (int r = ty; r < LZC; r += 8) {
        size_t idx = (size_t)r * LXC + col;
        S[idx] = __expf(S[idx] - m) * inv;
    }
}

// ---------------------------------------------------------------------------
// Launch: q = Wq@X+bq; k = Wk@Z+bk; v = Wv@Z+bv;
//         s = mask_scale(k^T q); softmax cols; out = v @ s
// ---------------------------------------------------------------------------
extern "C" void kernel_launch(void* const* d_in, const int* in_sizes, int n_in,
                              void* d_out, int out_size) {
    const float* X    = (const float*)d_in[0];
    const float* Z    = (const float*)d_in[1];
    const void*  mask = d_in[2];
    const float* Wq   = (const float*)d_in[3];
    const float* bq   = (const float*)d_in[4];
    const float* Wk   = (const float*)d_in[5];
    const float* bk   = (const float*)d_in[6];
    const float* Wv   = (const float*)d_in[7];
    const float* bv   = (const float*)d_in[8];
    float* out = (float*)d_out;

    float *q, *k, *v, *s;
    cudaGetSymbolAddress((void**)&q, g_q);
    cudaGetSymbolAddress((void**)&k, g_k);
    cudaGetSymbolAddress((void**)&v, g_v);
    cudaGetSymbolAddress((void**)&s, g_s);

    detect_mask_kernel<<<1, 256>>>((const unsigned int*)mask);

    // q, k, v projections: (1024 x 1024) @ (1024 x 4096)
    sgemm_kernel<0, 0><<<dim3(LXC / 128, DAC / 128), 256>>>(Wq, X, q, DAC, LXC, DAC, bq, nullptr);
    sgemm_kernel<0, 0><<<dim3(LZC / 128, DAC / 128), 256>>>(Wk, Z, k, DAC, LZC, DAC, bk, nullptr);
    sgemm_kernel<0, 0><<<dim3(LZC / 128, DAC / 128), 256>>>(Wv, Z, v, DAC, LZC, DAC, bv, nullptr);

    // score (lz, lx) = k^T @ q, fused mask + scale
    sgemm_kernel<1, 1><<<dim3(LXC / 128, LZC / 128), 256>>>(k, q, s, LZC, LXC, DAC, nullptr, mask);

    // softmax over lz (in place)
    softmax_kernel<<<LXC / 32, 256>>>(s);

    // out (dout, lx) = v @ attn
    sgemm_kernel<0, 0><<<dim3(LXC / 128, DAC / 128), 256>>>(v, s, out, DAC, LXC, LZC, nullptr, nullptr);
}